// round 10
// baseline (speedup 1.0000x reference)
#include <cuda_runtime.h>

// CBOW negative-sampling loss, round 9: fused single kernel, fence-free completion.
// ctx [B,CTX] i32, pos [B] i32, neg [B,NEG] i32, inW [V,D] f32, outW [V,D] f32 -> scalar f32.
#define VOCAB 50000
#define DIM   50
#define BATCH 131072
#define CTX   10
#define NEG   10

#define THREADS  128
#define WPB      (THREADS / 32)          // 4 samples per block
#define NBLOCKS  (BATCH / WPB)           // 32768
#define PER_T4   (NBLOCKS / 4 / THREADS) // 64 float4 per finalizer thread

#define RSTRIDE  28                      // 28 floats = 112B rows (16B aligned)

__device__ __align__(16) float g_part[NBLOCKS];  // per-block loss partials
__device__ unsigned            g_cnt = 0;        // completion counter (self-resetting)

// Release-ordered counter increment: orders the prior st.global.cg partial store
// WITHOUT a gpu-scope fence in producers (no CCTL.IVALL -> L1D stays warm).
__device__ __forceinline__ unsigned atom_inc_release(unsigned* p) {
    unsigned old;
    asm volatile("atom.global.release.gpu.add.u32 %0, [%1], 1;"
                 : "=r"(old) : "l"(p) : "memory");
    return old;
}

__global__ __launch_bounds__(THREADS, 12)    // ~42 regs -> 1536 thr/SM (75% occ)
void cbow_fused(const int* __restrict__ ctx,
                const int* __restrict__ pos,
                const int* __restrict__ neg,
                const float* __restrict__ inW,
                const float* __restrict__ outW,
                float* __restrict__ out)
{
    __shared__ int s_ctx[WPB * CTX];
    __shared__ int s_neg[WPB * NEG];
    __shared__ int s_pos[WPB];
    __shared__ __align__(16) float s_red[WPB][11 * RSTRIDE];
    __shared__ float s_wl[WPB];
    __shared__ bool  s_last;

    const int tid  = threadIdx.x;
    const int lane = tid & 31;
    const int warp = tid >> 5;
    const int B0   = blockIdx.x * WPB;
    const unsigned FULL = 0xffffffffu;

    // ---- stage this block's indices, coalesced ----
    if (tid < WPB * CTX) s_ctx[tid] = __ldg(&ctx[B0 * CTX + tid]);
    if (tid < WPB * NEG) s_neg[tid] = __ldg(&neg[B0 * NEG + tid]);
    if (tid < WPB)       s_pos[tid] = __ldg(&pos[B0 + tid]);
    __syncthreads();

    const float2* __restrict__ inW2  = (const float2*)inW;
    const float2* __restrict__ outW2 = (const float2*)outW;
    const bool act = (lane < 25);            // 25 lanes x float2 = 50 dims

    // ---- context mean: 2 groups of 5 loads, fold immediately (low live regs) ----
    float2 cv = make_float2(0.f, 0.f);
    #pragma unroll
    for (int g = 0; g < 2; g++) {
        float2 t[5];
        #pragma unroll
        for (int c = 0; c < 5; c++) {
            int r = s_ctx[warp * CTX + g * 5 + c];
            t[c] = act ? __ldg(&inW2[r * 25 + lane]) : make_float2(0.f, 0.f);
        }
        #pragma unroll
        for (int c = 0; c < 5; c++) { cv.x += t[c].x; cv.y += t[c].y; }
    }
    cv.x *= (1.0f / CTX);
    cv.y *= (1.0f / CTX);

    // ---- 11 out_embed dots: 3 groups (4/4/3), fold to p[] immediately ----
    float p[NEG + 1];
    {
        float2 t[4];
        {
            int r = s_pos[warp];
            t[0] = act ? __ldg(&outW2[r * 25 + lane]) : make_float2(0.f, 0.f);
        }
        #pragma unroll
        for (int k = 0; k < 3; k++) {
            int r = s_neg[warp * NEG + k];
            t[k + 1] = act ? __ldg(&outW2[r * 25 + lane]) : make_float2(0.f, 0.f);
        }
        #pragma unroll
        for (int j = 0; j < 4; j++) p[j] = cv.x * t[j].x + cv.y * t[j].y;
    }
    {
        float2 t[4];
        #pragma unroll
        for (int k = 0; k < 4; k++) {
            int r = s_neg[warp * NEG + 3 + k];
            t[k] = act ? __ldg(&outW2[r * 25 + lane]) : make_float2(0.f, 0.f);
        }
        #pragma unroll
        for (int j = 0; j < 4; j++) p[4 + j] = cv.x * t[j].x + cv.y * t[j].y;
    }
    {
        float2 t[3];
        #pragma unroll
        for (int k = 0; k < 3; k++) {
            int r = s_neg[warp * NEG + 7 + k];
            t[k] = act ? __ldg(&outW2[r * 25 + lane]) : make_float2(0.f, 0.f);
        }
        #pragma unroll
        for (int j = 0; j < 3; j++) p[8 + j] = cv.x * t[j].x + cv.y * t[j].y;
    }

    // ---- smem transpose: lane j owns dot j ----
    if (act) {
        #pragma unroll
        for (int j = 0; j <= NEG; j++)
            s_red[warp][j * RSTRIDE + lane] = p[j];
    }
    __syncwarp();

    float term = 0.f;
    if (lane <= NEG) {
        const float* row = &s_red[warp][lane * RSTRIDE];
        float4 a = *(const float4*)(row);
        float4 b = *(const float4*)(row + 4);
        float4 c = *(const float4*)(row + 8);
        float4 d = *(const float4*)(row + 12);
        float4 e = *(const float4*)(row + 16);
        float4 f = *(const float4*)(row + 20);
        float s = ((a.x + a.y) + (a.z + a.w)) + ((b.x + b.y) + (b.z + b.w))
                + ((c.x + c.y) + (c.z + c.w)) + ((d.x + d.y) + (d.z + d.w))
                + ((e.x + e.y) + (e.z + e.w)) + ((f.x + f.y) + (f.z + f.w))
                + row[24];
        float arg = (lane == 0) ? s : -s;    // pos: +score, negs: -score
        float sg  = 1.0f / (1.0f + __expf(-arg));
        term = __logf(sg + 1e-10f);
    }
    #pragma unroll
    for (int o = 8; o > 0; o >>= 1)          // sum lanes 0..15 (11..15 zero)
        term += __shfl_xor_sync(FULL, term, o);

    if (lane == 0) s_wl[warp] = term;
    __syncthreads();

    // ---- per-block partial, release-ordered completion count (no gpu fence) ----
    if (tid == 0) {
        float t = (s_wl[0] + s_wl[1]) + (s_wl[2] + s_wl[3]);
        __stcg(&g_part[blockIdx.x], t);              // L2-direct store
        unsigned old = atom_inc_release(&g_cnt);     // orders the store above
        s_last = (old == NBLOCKS - 1);
    }
    __syncthreads();
    if (!s_last) return;

    // ---- last block only: one acquire fence, then fixed-order sum of 32768 partials ----
    if (tid == 0) asm volatile("fence.acquire.gpu;" ::: "memory");
    __syncthreads();
    {
        const float4* __restrict__ p4 = (const float4*)g_part;   // 8192 float4
        float t = 0.f;
        #pragma unroll
        for (int i = 0; i < PER_T4; i++) {                       // 64 float4/thread
            float4 v = __ldcg(&p4[tid + i * THREADS]);
            t += ((v.x + v.y) + (v.z + v.w));
        }
        #pragma unroll
        for (int o = 16; o > 0; o >>= 1)
            t += __shfl_xor_sync(FULL, t, o);

        __shared__ float s_fin[WPB];
        if (lane == 0) s_fin[warp] = t;
        __syncthreads();
        if (tid == 0) {
            float v = (s_fin[0] + s_fin[1]) + (s_fin[2] + s_fin[3]);
            out[0] = -v / (float)BATCH;
            g_cnt = 0;                        // reset for next graph replay
        }
    }
}

extern "C" void kernel_launch(void* const* d_in, const int* in_sizes, int n_in,
                              void* d_out, int out_size)
{
    const int*   ctx  = (const int*)d_in[0];   // [B, CTX]
    const int*   pos  = (const int*)d_in[1];   // [B]
    const int*   neg  = (const int*)d_in[2];   // [B, NEG]
    const float* inW  = (const float*)d_in[3]; // [VOCAB, DIM]
    const float* outW = (const float*)d_in[4]; // [VOCAB, DIM]
    float* out = (float*)d_out;

    cbow_fused<<<NBLOCKS, THREADS>>>(ctx, pos, neg, inW, outW, out);
}